// round 2
// baseline (speedup 1.0000x reference)
#include <cuda_runtime.h>
#include <math.h>

#define T_LEN 1024
#define NBATCH 256

// ---------------- device scratch (no allocations allowed) ----------------
__device__ __align__(16) float g_M[T_LEN * 128];     // M_t = A*SBR_t, [t][16][8]
__device__ __align__(16) float g_Minv[T_LEN * 64];   // inv(innov_var_t), [t][8][8]
__device__ __align__(16) float g_logdet[T_LEN];      // logdet(innov_var_t)
__device__ int g_conv;                               // last t actually computed

// =====================================================================
// Phase 1: batch-independent Riccati recursion, single block, 256 thr.
// =====================================================================
__global__ void __launch_bounds__(256, 1)
riccati_kernel(const float* __restrict__ A, const float* __restrict__ B,
               const float* __restrict__ U, const float* __restrict__ V,
               const float* __restrict__ W, const float* __restrict__ A0)
{
    __shared__ float sS[16][16];   // current prior covariance
    __shared__ float sBS[8][16];   // B*S
    __shared__ float sAug[8][16];  // [innov_var | I] -> [I | inv]
    __shared__ float sSBR[16][8];  // S B^T inv
    __shared__ float sPS[16][16];  // post_S (also reused as X temp)
    __shared__ float sAP[16][16];  // A*post_S (also temp for W*U)
    __shared__ float sA[16][16], sB[8][16], sQ[16][16], sV[8][8];
    __shared__ float sW[16][16], sU[16][16];
    __shared__ int s_max;       // bitcast float atomicMax (diffs >= 0)
    __shared__ int s_convcount;
    __shared__ int s_done;

    const int tid = threadIdx.x;
    {
        int i = tid >> 4, j = tid & 15;
        sA[i][j] = A[tid];
        sW[i][j] = W[tid];
        sU[i][j] = U[tid];
        sS[i][j] = A0[tid];          // S0 = A0
    }
    if (tid < 128) sB[tid >> 4][tid & 15] = B[tid];
    if (tid < 64)  sV[tid >> 3][tid & 7]  = V[tid];
    if (tid == 0) { s_convcount = 0; s_done = 0; }
    __syncthreads();

    // Q = W U W^T  (WU in sAP temp)
    {
        int i = tid >> 4, j = tid & 15;
        float acc = 0.f;
        #pragma unroll
        for (int k = 0; k < 16; ++k) acc += sW[i][k] * sU[k][j];
        sAP[i][j] = acc;
    }
    __syncthreads();
    {
        int i = tid >> 4, j = tid & 15;
        float acc = 0.f;
        #pragma unroll
        for (int k = 0; k < 16; ++k) acc += sAP[i][k] * sW[j][k];
        sQ[i][j] = acc;
    }
    __syncthreads();

    int conv_t = T_LEN - 1;

    for (int t = 0; t < T_LEN; ++t) {
        // ---- stage 1: BS[j][k] = sum_l B[j][l] S[l][k]
        if (tid < 128) {
            int j = tid >> 4, k = tid & 15;
            float acc = 0.f;
            #pragma unroll
            for (int l = 0; l < 16; ++l) acc += sB[j][l] * sS[l][k];
            sBS[j][k] = acc;
        }
        __syncthreads();

        // ---- stage 2: Aug = [ B S B^T + V | I ]
        if (tid < 128) {
            int j = tid >> 4, c = tid & 15;
            if (c < 8) {
                float acc = sV[j][c];
                #pragma unroll
                for (int k = 0; k < 16; ++k) acc += sBS[j][k] * sB[c][k];
                sAug[j][c] = acc;
            } else {
                sAug[j][c] = (c - 8 == j) ? 1.f : 0.f;
            }
        }
        __syncthreads();

        // ---- stage 3: Gauss-Jordan inversion (8x8 SPD, no pivoting)
        float ld = 0.f;  // thread 0 accumulates logdet
        #pragma unroll
        for (int k = 0; k < 8; ++k) {
            float p = sAug[k][k];
            float rowk = 0.f, f = 0.f;
            int j = tid >> 4, c = tid & 15;
            if (tid < 128) { rowk = sAug[k][c]; f = sAug[j][k]; }
            __syncthreads();
            if (tid < 128) {
                float pin = 1.f / p;
                if (j == k) sAug[j][c] = rowk * pin;
                else        sAug[j][c] = sAug[j][c] - (f * pin) * rowk;
            }
            if (tid == 0) ld += logf(fabsf(p));
            __syncthreads();
        }
        // inverse now lives in sAug[.][8..15]

        // ---- stage 4: SBR[i][j] = sum_m (S B^T)[i][m] inv[m][j] ; S B^T = BS^T (S symm.)
        if (tid < 128) {
            int i = tid >> 3, j = tid & 7;
            float acc = 0.f;
            #pragma unroll
            for (int m = 0; m < 8; ++m) acc += sBS[m][i] * sAug[m][8 + j];
            sSBR[i][j] = acc;
        }
        __syncthreads();

        // ---- stage 5: post_S = S - SBR*BS ; write tables M, Minv, logdet
        {
            int i = tid >> 4, k = tid & 15;
            float acc = 0.f;
            #pragma unroll
            for (int j = 0; j < 8; ++j) acc += sSBR[i][j] * sBS[j][k];
            sPS[i][k] = sS[i][k] - acc;
        }
        if (tid < 128) {           // M[i][j] = sum_k A[i][k] SBR[k][j]
            int i = tid >> 3, j = tid & 7;
            float acc = 0.f;
            #pragma unroll
            for (int k = 0; k < 16; ++k) acc += sA[i][k] * sSBR[k][j];
            g_M[t * 128 + tid] = acc;
        }
        if (tid < 64) {            // Minv
            int j = tid >> 3, m = tid & 7;
            g_Minv[t * 64 + tid] = sAug[j][8 + m];
        }
        if (tid == 0) g_logdet[t] = ld;
        __syncthreads();

        // ---- stage 6: AP = A * post_S
        {
            int i = tid >> 4, k = tid & 15;
            float acc = 0.f;
            #pragma unroll
            for (int l = 0; l < 16; ++l) acc += sA[i][l] * sPS[l][k];
            sAP[i][k] = acc;
        }
        __syncthreads();

        // ---- stage 7: X = AP*A^T + Q  (into sPS temp)
        {
            int i = tid >> 4, k = tid & 15;
            float acc = sQ[i][k];
            #pragma unroll
            for (int l = 0; l < 16; ++l) acc += sAP[i][l] * sA[k][l];
            sPS[i][k] = acc;
        }
        if (tid == 0) s_max = 0;
        __syncthreads();

        // ---- stage 8: symmetrize, diff, store new S
        {
            int i = tid >> 4, k = tid & 15;
            float snew = 0.5f * (sPS[i][k] + sPS[k][i]);
            float d = fabsf(snew - sS[i][k]);
            atomicMax(&s_max, __float_as_int(d));
            sS[i][k] = snew;
        }
        __syncthreads();
        if (tid == 0) {
            float md = __int_as_float(s_max);
            if (md < 2e-6f) { if (++s_convcount >= 2) s_done = 1; }
            else s_convcount = 0;
        }
        __syncthreads();
        if (s_done) { conv_t = t; break; }
    }

    if (tid == 0) g_conv = conv_t;
}

// =====================================================================
// Fill kernel: replicate converged tables to t > g_conv
// =====================================================================
__global__ void fill_kernel()
{
    int t = blockIdx.x;
    int c = g_conv;
    if (t <= c) return;
    int tid = threadIdx.x;                 // 128 threads
    g_M[t * 128 + tid] = g_M[c * 128 + tid];
    if (tid < 64) g_Minv[t * 64 + tid] = g_Minv[c * 64 + tid];
    if (tid == 0) g_logdet[t] = g_logdet[c];
}

// =====================================================================
// Phase 2: per-batch mean recursion + NLL. One warp = 2 batches.
// Lane layout: g = lane>>4 selects batch, i = lane&15 is state index.
// mu replicated across lanes of a 16-lane group.
// =====================================================================
__global__ void __launch_bounds__(32, 1)
mean_nll_kernel(const float* __restrict__ x, const float* __restrict__ a,
                const float* __restrict__ b, const float* __restrict__ A,
                const float* __restrict__ B, const float* __restrict__ a0,
                float* __restrict__ out)
{
    const unsigned FULL = 0xffffffffu;
    const float LOG2PI = 1.8378770664093453f;

    int lane = threadIdx.x;
    int g = lane >> 4, i = lane & 15;
    int batch = blockIdx.x * 2 + g;

    float Arow[16], Brow[16], mu[16];
    #pragma unroll
    for (int k = 0; k < 16; ++k) Arow[k] = A[i * 16 + k];
    #pragma unroll
    for (int k = 0; k < 16; ++k) Brow[k] = (i < 8) ? B[i * 16 + k] : 0.f;
    #pragma unroll
    for (int k = 0; k < 16; ++k) mu[k] = a0[k];

    float a_i = a[i];
    float b_i = (i < 8) ? b[i] : 0.f;

    const float* xb = x + (size_t)batch * T_LEN * 8;
    float nll = 0.f;

    for (int t = 0; t < T_LEN; ++t) {
        // innovation component (valid for i<8; zero otherwise since Brow=0)
        float xv = (i < 8) ? xb[t * 8 + i] : 0.f;
        float dot = 0.f;
        #pragma unroll
        for (int k = 0; k < 16; ++k) dot += Brow[k] * mu[k];
        float innov = xv - b_i - dot;

        // broadcast innovation vector within the 16-lane group
        float iv[8];
        #pragma unroll
        for (int j = 0; j < 8; ++j) iv[j] = __shfl_sync(FULL, innov, j, 16);

        // quadratic form innov^T Minv innov (lanes 0..7 contribute)
        int r = i & 7;
        const float4* mp = (const float4*)(g_Minv + t * 64 + r * 8);
        float4 m0 = mp[0], m1 = mp[1];
        float q = m0.x * iv[0] + m0.y * iv[1] + m0.z * iv[2] + m0.w * iv[3]
                + m1.x * iv[4] + m1.y * iv[5] + m1.z * iv[6] + m1.w * iv[7];
        float s = (i < 8) ? iv[i] * q : 0.f;
        #pragma unroll
        for (int off = 1; off < 16; off <<= 1)
            s += __shfl_xor_sync(FULL, s, off, 16);

        float ldet = g_logdet[t];
        nll += 0.5f * (s + ldet + 8.f * LOG2PI);

        // mu update: mu' = a + A mu + M innov
        const float4* Mp = (const float4*)(g_M + t * 128 + i * 8);
        float4 M0 = Mp[0], M1 = Mp[1];
        float mn = a_i;
        #pragma unroll
        for (int k = 0; k < 16; ++k) mn += Arow[k] * mu[k];
        mn += M0.x * iv[0] + M0.y * iv[1] + M0.z * iv[2] + M0.w * iv[3]
            + M1.x * iv[4] + M1.y * iv[5] + M1.z * iv[6] + M1.w * iv[7];

        // re-replicate mu
        #pragma unroll
        for (int k = 0; k < 16; ++k) mu[k] = __shfl_sync(FULL, mn, k, 16);
    }

    if (i == 0) out[batch] = nll;
}

// =====================================================================
// Launcher
// =====================================================================
extern "C" void kernel_launch(void* const* d_in, const int* in_sizes, int n_in,
                              void* d_out, int out_size)
{
    const float* x  = (const float*)d_in[0];
    const float* a  = (const float*)d_in[1];
    const float* b  = (const float*)d_in[2];
    const float* A  = (const float*)d_in[3];
    const float* B  = (const float*)d_in[4];
    const float* U  = (const float*)d_in[5];
    const float* V  = (const float*)d_in[6];
    const float* W  = (const float*)d_in[7];
    const float* a0 = (const float*)d_in[8];
    const float* A0 = (const float*)d_in[9];
    float* out = (float*)d_out;

    riccati_kernel<<<1, 256>>>(A, B, U, V, W, A0);
    fill_kernel<<<T_LEN, 128>>>();
    mean_nll_kernel<<<NBATCH / 2, 32>>>(x, a, b, A, B, a0, out);
}

// round 3
// speedup vs baseline: 1.7144x; 1.7144x over previous
#include <cuda_runtime.h>
#include <math.h>

#define T_LEN   1024
#define NBATCH  256
#define NCHUNK  64
#define CHUNKL  16

// ---------------- device scratch (no allocations allowed) ----------------
__device__ __align__(16) float g_M[T_LEN * 128];       // M_t = A*SBR_t, [t][16][8]
__device__ __align__(16) float g_Minv[T_LEN * 64];     // inv(innov_var_t), [t][8][8]
__device__ __align__(16) float g_logdet[T_LEN];        // logdet(innov_var_t)
__device__ __align__(16) float g_H[NCHUNK * 256];      // chunk transition 16x16
__device__ __align__(16) float g_p[NCHUNK * NBATCH * 16];        // zero-init chunk response
__device__ __align__(16) float g_mustart[NCHUNK * NBATCH * 16];  // chunk entry states
__device__ __align__(16) float g_partial[NCHUNK * NBATCH];       // per-chunk nll
__device__ int g_conv;                                  // last t actually computed

// =====================================================================
// Phase 1: batch-independent Riccati recursion. Single block, 256 thr.
// 16 barriers/step; unnormalized register-GJ inversion; single-hit
// convergence freeze at 2e-5.
// =====================================================================
__global__ void __launch_bounds__(256, 1)
riccati_kernel(const float* __restrict__ A, const float* __restrict__ B,
               const float* __restrict__ U, const float* __restrict__ V,
               const float* __restrict__ W, const float* __restrict__ A0)
{
    __shared__ float sS[16][16];   // current prior covariance
    __shared__ float sBS[8][16];   // B*S
    __shared__ float sGJ[8][16];   // augmented [innov_var | I]
    __shared__ float sInv[8][8];   // inverse
    __shared__ float sSBR[16][8];  // S B^T inv
    __shared__ float sPS[16][16];  // post_S (also WU temp)
    __shared__ float sAP[16][16];  // A*post_S
    __shared__ float sA[16][16], sB[8][16], sQ[16][16], sV[8][8];
    __shared__ int s_max;          // bitcast float atomicMax (diffs >= 0)
    __shared__ int s_done;

    const int tid = threadIdx.x;
    const int i16 = tid >> 4, j16 = tid & 15;     // 256-thread (i,j)
    const int jr = tid >> 4, cr = tid & 15;       // 128-thread (row, col)

    sA[i16][j16] = A[tid];
    sS[i16][j16] = A0[tid];                       // S0 = A0
    if (tid < 128) sB[tid >> 4][tid & 15] = B[tid];
    if (tid < 64)  sV[tid >> 3][tid & 7]  = V[tid];
    if (tid == 0) s_done = 0;
    __syncthreads();

    // Q = W U W^T  (WU staged in sPS)
    {
        float acc = 0.f;
        #pragma unroll
        for (int k = 0; k < 16; ++k) acc += W[i16 * 16 + k] * U[k * 16 + j16];
        sPS[i16][j16] = acc;
    }
    __syncthreads();
    {
        float acc = 0.f;
        #pragma unroll
        for (int k = 0; k < 16; ++k) acc += sPS[i16][k] * W[j16 * 16 + k];
        sQ[i16][j16] = acc;
    }
    __syncthreads();

    int conv_t = T_LEN - 1;

    for (int t = 0; t < T_LEN; ++t) {
        // ---- s1: BS = B*S
        if (tid < 128) {
            float acc = 0.f;
            #pragma unroll
            for (int l = 0; l < 16; ++l) acc += sB[jr][l] * sS[l][cr];
            sBS[jr][cr] = acc;
        }
        __syncthreads();

        // ---- s2: Aug = [B S B^T + V | I], register copy v
        float v = 0.f;
        if (tid < 128) {
            if (cr < 8) {
                float acc = sV[jr][cr];
                #pragma unroll
                for (int k = 0; k < 16; ++k) acc += sBS[jr][k] * sB[cr][k];
                v = acc;
            } else {
                v = (cr - 8 == jr) ? 1.f : 0.f;
            }
            sGJ[jr][cr] = v;
        }
        __syncthreads();

        // ---- s3: unnormalized Gauss-Jordan, 1 barrier per pivot.
        // Row k is never written during iteration k -> no read/write race.
        float ld = 0.f;
        #pragma unroll
        for (int k = 0; k < 8; ++k) {
            if (tid < 128) {
                float p    = sGJ[k][k];
                float rowk = sGJ[k][cr];
                float f    = __shfl_sync(0xffffffffu, v, k, 16);  // own row, col k
                if (jr != k) {
                    v = fmaf(-f * __frcp_rn(p), rowk, v);
                    sGJ[jr][cr] = v;
                }
            }
            if (tid == 0) ld += logf(sGJ[k][k]);
            __syncthreads();
        }

        // ---- s4: deferred pivot scale -> inverse; write Minv, logdet
        if (tid < 128 && cr >= 8) {
            float inv = v * __frcp_rn(sGJ[jr][jr]);
            sInv[jr][cr - 8] = inv;
            g_Minv[t * 64 + jr * 8 + (cr - 8)] = inv;
        }
        if (tid == 0) g_logdet[t] = ld;
        __syncthreads();

        // ---- s5: SBR[i][j] = sum_m BS[m][i] * Inv[m][j]  (S B^T = BS^T)
        if (tid < 128) {
            int i = tid >> 3, j = tid & 7;
            float acc = 0.f;
            #pragma unroll
            for (int m = 0; m < 8; ++m) acc += sBS[m][i] * sInv[m][j];
            sSBR[i][j] = acc;
        }
        __syncthreads();

        // ---- s6: tid<128 -> post_S (2 elems each); tid>=128 -> M table
        if (tid < 128) {
            #pragma unroll
            for (int e = tid; e < 256; e += 128) {
                int i = e >> 4, k = e & 15;
                float acc = sS[i][k];
                #pragma unroll
                for (int j = 0; j < 8; ++j) acc -= sSBR[i][j] * sBS[j][k];
                sPS[i][k] = acc;
            }
        } else {
            int idx = tid - 128;
            int i = idx >> 3, j = idx & 7;
            float acc = 0.f;
            #pragma unroll
            for (int k = 0; k < 16; ++k) acc += sA[i][k] * sSBR[k][j];
            g_M[t * 128 + idx] = acc;
        }
        __syncthreads();

        // ---- s7: AP = A * post_S
        {
            float acc = 0.f;
            #pragma unroll
            for (int l = 0; l < 16; ++l) acc += sA[i16][l] * sPS[l][j16];
            sAP[i16][j16] = acc;
        }
        if (tid == 0) s_max = 0;
        __syncthreads();

        // ---- s8: Snew = Q + sym(AP*A^T); both dots per thread, no extra barrier
        {
            float x1 = 0.f, x2 = 0.f;
            #pragma unroll
            for (int m = 0; m < 16; ++m) {
                x1 += sAP[i16][m] * sA[j16][m];
                x2 += sAP[j16][m] * sA[i16][m];
            }
            float snew = sQ[i16][j16] + 0.5f * (x1 + x2);
            float d = fabsf(snew - sS[i16][j16]);
            atomicMax(&s_max, __float_as_int(d));
            sS[i16][j16] = snew;
        }
        __syncthreads();
        if (tid == 0 && __int_as_float(s_max) < 2e-5f) s_done = 1;
        __syncthreads();
        if (s_done) { conv_t = t; break; }
    }

    if (tid == 0) g_conv = conv_t;
}

// =====================================================================
// Fill: replicate converged tables to t > g_conv
// =====================================================================
__global__ void fill_kernel()
{
    int t = blockIdx.x;
    int c = g_conv;
    if (t <= c) return;
    int tid = threadIdx.x;                 // 128 threads
    g_M[t * 128 + tid] = g_M[c * 128 + tid];
    if (tid < 64) g_Minv[t * 64 + tid] = g_Minv[c * 64 + tid];
    if (tid == 0) g_logdet[t] = g_logdet[c];
}

// =====================================================================
// Chunk transition products: H_c = G_{15} ... G_0, G_t = A - M_t * B
// One block per chunk, 256 threads (one per H element).
// =====================================================================
__global__ void __launch_bounds__(256, 1)
chunkH_kernel(const float* __restrict__ A, const float* __restrict__ B)
{
    __shared__ float sG[16][16], sH[2][16][16], sB[8][16];
    int tid = threadIdx.x;
    int i = tid >> 4, c = tid & 15;
    float a_ic = A[tid];
    if (tid < 128) sB[tid >> 4][tid & 15] = B[tid];
    sH[0][i][c] = (i == c) ? 1.f : 0.f;
    __syncthreads();

    int cur = 0;
    for (int s = 0; s < CHUNKL; ++s) {
        int t = blockIdx.x * CHUNKL + s;
        const float* Mrow = g_M + t * 128 + i * 8;
        float g = a_ic;
        #pragma unroll
        for (int j = 0; j < 8; ++j) g -= Mrow[j] * sB[j][c];
        sG[i][c] = g;
        __syncthreads();
        float acc = 0.f;
        #pragma unroll
        for (int k = 0; k < 16; ++k) acc += sG[i][k] * sH[cur][k][c];
        sH[cur ^ 1][i][c] = acc;
        cur ^= 1;
        __syncthreads();
    }
    g_H[blockIdx.x * 256 + tid] = sH[cur][i][c];
}

// =====================================================================
// Pass B: zero-init chunk responses. grid = 64 chunks * 32 blocks,
// block = 128 thr = 4 warps, warp = 2 batches (16 lanes each).
// =====================================================================
__global__ void __launch_bounds__(128)
passB_kernel(const float* __restrict__ x, const float* __restrict__ a,
             const float* __restrict__ b, const float* __restrict__ A,
             const float* __restrict__ B)
{
    const unsigned FULL = 0xffffffffu;
    int lane = threadIdx.x & 31, warp = threadIdx.x >> 5;
    int chunk = blockIdx.x >> 5, pg = blockIdx.x & 31;
    int g = lane >> 4, i = lane & 15;
    int batch = (pg * 4 + warp) * 2 + g;

    float Arow[16], Brow[16], mu[16];
    #pragma unroll
    for (int k = 0; k < 16; ++k) Arow[k] = A[i * 16 + k];
    #pragma unroll
    for (int k = 0; k < 16; ++k) Brow[k] = (i < 8) ? B[i * 16 + k] : 0.f;
    #pragma unroll
    for (int k = 0; k < 16; ++k) mu[k] = 0.f;
    float a_i = a[i];
    float b_i = (i < 8) ? b[i] : 0.f;

    const float* xb = x + (size_t)batch * T_LEN * 8;
    int t0 = chunk * CHUNKL;

    for (int s = 0; s < CHUNKL; ++s) {
        int t = t0 + s;
        float xv = (i < 8) ? xb[t * 8 + i] : 0.f;
        float dot = 0.f;
        #pragma unroll
        for (int k = 0; k < 16; ++k) dot += Brow[k] * mu[k];
        float innov = xv - b_i - dot;

        float iv[8];
        #pragma unroll
        for (int j = 0; j < 8; ++j) iv[j] = __shfl_sync(FULL, innov, j, 16);

        const float4* Mp = (const float4*)(g_M + t * 128 + i * 8);
        float4 M0 = Mp[0], M1 = Mp[1];
        float mn = a_i;
        #pragma unroll
        for (int k = 0; k < 16; ++k) mn += Arow[k] * mu[k];
        mn += M0.x * iv[0] + M0.y * iv[1] + M0.z * iv[2] + M0.w * iv[3]
            + M1.x * iv[4] + M1.y * iv[5] + M1.z * iv[6] + M1.w * iv[7];

        #pragma unroll
        for (int k = 0; k < 16; ++k) mu[k] = __shfl_sync(FULL, mn, k, 16);
    }
    g_p[(chunk * NBATCH + batch) * 16 + i] = mu[i];
}

// =====================================================================
// Combine: sequential over 64 chunks, parallel over batches.
// mu_start[c+1] = H_c * mu_start[c] + p_c
// =====================================================================
__global__ void __launch_bounds__(32, 1)
combine_kernel(const float* __restrict__ a0)
{
    const unsigned FULL = 0xffffffffu;
    int lane = threadIdx.x;
    int g = lane >> 4, i = lane & 15;
    int batch = blockIdx.x * 2 + g;

    float mu[16];
    #pragma unroll
    for (int k = 0; k < 16; ++k) mu[k] = a0[k];

    for (int c = 0; c < NCHUNK; ++c) {
        g_mustart[(c * NBATCH + batch) * 16 + i] = mu[i];
        const float4* Hp = (const float4*)(g_H + c * 256 + i * 16);
        float4 h0 = Hp[0], h1 = Hp[1], h2 = Hp[2], h3 = Hp[3];
        float mn = g_p[(c * NBATCH + batch) * 16 + i];
        mn += h0.x * mu[0]  + h0.y * mu[1]  + h0.z * mu[2]  + h0.w * mu[3]
            + h1.x * mu[4]  + h1.y * mu[5]  + h1.z * mu[6]  + h1.w * mu[7]
            + h2.x * mu[8]  + h2.y * mu[9]  + h2.z * mu[10] + h2.w * mu[11]
            + h3.x * mu[12] + h3.y * mu[13] + h3.z * mu[14] + h3.w * mu[15];
        #pragma unroll
        for (int k = 0; k < 16; ++k) mu[k] = __shfl_sync(FULL, mn, k, 16);
    }
}

// =====================================================================
// Pass D: per-chunk NLL from true chunk-entry states.
// =====================================================================
__global__ void __launch_bounds__(128)
passD_kernel(const float* __restrict__ x, const float* __restrict__ a,
             const float* __restrict__ b, const float* __restrict__ A,
             const float* __restrict__ B)
{
    const unsigned FULL = 0xffffffffu;
    const float LOG2PI = 1.8378770664093453f;
    int lane = threadIdx.x & 31, warp = threadIdx.x >> 5;
    int chunk = blockIdx.x >> 5, pg = blockIdx.x & 31;
    int g = lane >> 4, i = lane & 15;
    int batch = (pg * 4 + warp) * 2 + g;

    float Arow[16], Brow[16], mu[16];
    #pragma unroll
    for (int k = 0; k < 16; ++k) Arow[k] = A[i * 16 + k];
    #pragma unroll
    for (int k = 0; k < 16; ++k) Brow[k] = (i < 8) ? B[i * 16 + k] : 0.f;
    {
        float mi = g_mustart[(chunk * NBATCH + batch) * 16 + i];
        #pragma unroll
        for (int k = 0; k < 16; ++k) mu[k] = __shfl_sync(FULL, mi, k, 16);
    }
    float a_i = a[i];
    float b_i = (i < 8) ? b[i] : 0.f;

    const float* xb = x + (size_t)batch * T_LEN * 8;
    int t0 = chunk * CHUNKL;
    float nll = 0.f;

    for (int s = 0; s < CHUNKL; ++s) {
        int t = t0 + s;
        float xv = (i < 8) ? xb[t * 8 + i] : 0.f;
        float dot = 0.f;
        #pragma unroll
        for (int k = 0; k < 16; ++k) dot += Brow[k] * mu[k];
        float innov = xv - b_i - dot;

        float iv[8];
        #pragma unroll
        for (int j = 0; j < 8; ++j) iv[j] = __shfl_sync(FULL, innov, j, 16);

        // quadratic form (lanes 0..7 contribute)
        int r = i & 7;
        const float4* mp = (const float4*)(g_Minv + t * 64 + r * 8);
        float4 m0 = mp[0], m1 = mp[1];
        float q = m0.x * iv[0] + m0.y * iv[1] + m0.z * iv[2] + m0.w * iv[3]
                + m1.x * iv[4] + m1.y * iv[5] + m1.z * iv[6] + m1.w * iv[7];
        float sred = (i < 8) ? iv[i] * q : 0.f;
        #pragma unroll
        for (int off = 1; off < 16; off <<= 1)
            sred += __shfl_xor_sync(FULL, sred, off, 16);

        nll += 0.5f * (sred + g_logdet[t] + 8.f * LOG2PI);

        const float4* Mp = (const float4*)(g_M + t * 128 + i * 8);
        float4 M0 = Mp[0], M1 = Mp[1];
        float mn = a_i;
        #pragma unroll
        for (int k = 0; k < 16; ++k) mn += Arow[k] * mu[k];
        mn += M0.x * iv[0] + M0.y * iv[1] + M0.z * iv[2] + M0.w * iv[3]
            + M1.x * iv[4] + M1.y * iv[5] + M1.z * iv[6] + M1.w * iv[7];

        #pragma unroll
        for (int k = 0; k < 16; ++k) mu[k] = __shfl_sync(FULL, mn, k, 16);
    }

    if (i == 0) g_partial[chunk * NBATCH + batch] = nll;
}

// =====================================================================
// Reduce: out[b] = sum_c partial[c][b]   (deterministic order)
// =====================================================================
__global__ void __launch_bounds__(256)
reduce_kernel(float* __restrict__ out)
{
    int b = threadIdx.x;
    float s = 0.f;
    #pragma unroll 8
    for (int c = 0; c < NCHUNK; ++c) s += g_partial[c * NBATCH + b];
    out[b] = s;
}

// =====================================================================
// Launcher
// =====================================================================
extern "C" void kernel_launch(void* const* d_in, const int* in_sizes, int n_in,
                              void* d_out, int out_size)
{
    const float* x  = (const float*)d_in[0];
    const float* a  = (const float*)d_in[1];
    const float* b  = (const float*)d_in[2];
    const float* A  = (const float*)d_in[3];
    const float* B  = (const float*)d_in[4];
    const float* U  = (const float*)d_in[5];
    const float* V  = (const float*)d_in[6];
    const float* W  = (const float*)d_in[7];
    const float* a0 = (const float*)d_in[8];
    const float* A0 = (const float*)d_in[9];
    float* out = (float*)d_out;

    riccati_kernel<<<1, 256>>>(A, B, U, V, W, A0);
    fill_kernel<<<T_LEN, 128>>>();
    chunkH_kernel<<<NCHUNK, 256>>>(A, B);
    passB_kernel<<<NCHUNK * 32, 128>>>(x, a, b, A, B);
    combine_kernel<<<NBATCH / 2, 32>>>(a0);
    passD_kernel<<<NCHUNK * 32, 128>>>(x, a, b, A, B);
    reduce_kernel<<<1, 256>>>(out);
}

// round 4
// speedup vs baseline: 1.7924x; 1.0455x over previous
#include <cuda_runtime.h>
#include <math.h>

#define T_LEN   1024
#define NBATCH  256
#define NCHUNK  64
#define CHUNKL  16
#define RIC_CAP 512

// ---------------- device scratch (no allocations allowed) ----------------
__device__ __align__(16) float g_M[T_LEN * 128];       // M_t = A*SBR_t, [t][16][8]
__device__ __align__(16) float g_Minv[T_LEN * 64];     // inv(innov_var_t), [t][8][8]
__device__ __align__(16) float g_logdet[T_LEN];        // logdet(innov_var_t)
__device__ __align__(16) float g_G[T_LEN * 256];       // G_t = A - M_t*B, [t][16][16]
__device__ __align__(16) float g_atld[T_LEN * 16];     // atld_t = a - M_t*b
__device__ __align__(16) float g_H[NCHUNK * 256];      // chunk transition 16x16
__device__ __align__(16) float g_p[NCHUNK * NBATCH * 16];        // zero-init chunk response
__device__ __align__(16) float g_mustart[NCHUNK * NBATCH * 16];  // chunk entry states
__device__ __align__(16) float g_partial[NCHUNK * NBATCH];       // per-chunk nll
__device__ int g_conv;                                  // last t actually computed

// =====================================================================
// Phase 1: batch-independent Riccati recursion. Single block, 256 thr.
// Hard cap RIC_CAP steps; early-exit check every 8 steps at 3e-5.
// =====================================================================
__global__ void __launch_bounds__(256, 1)
riccati_kernel(const float* __restrict__ A, const float* __restrict__ B,
               const float* __restrict__ U, const float* __restrict__ V,
               const float* __restrict__ W, const float* __restrict__ A0)
{
    __shared__ float sS[16][16];   // current prior covariance
    __shared__ float sBS[8][16];   // B*S
    __shared__ float sGJ[8][16];   // augmented [innov_var | I]
    __shared__ float sInv[8][8];   // inverse
    __shared__ float sSBR[16][8];  // S B^T inv
    __shared__ float sPS[16][16];  // post_S (also WU temp)
    __shared__ float sAP[16][16];  // A*post_S
    __shared__ float sA[16][16], sB[8][16], sQ[16][16], sV[8][8];
    __shared__ int s_max;          // bitcast float atomicMax (diffs >= 0)
    __shared__ int s_done;

    const int tid = threadIdx.x;
    const int i16 = tid >> 4, j16 = tid & 15;     // 256-thread (i,j)
    const int jr = tid >> 4, cr = tid & 15;       // 128-thread (row, col)

    sA[i16][j16] = A[tid];
    sS[i16][j16] = A0[tid];                       // S0 = A0
    if (tid < 128) sB[tid >> 4][tid & 15] = B[tid];
    if (tid < 64)  sV[tid >> 3][tid & 7]  = V[tid];
    if (tid == 0) s_done = 0;
    __syncthreads();

    // Q = W U W^T  (WU staged in sPS)
    {
        float acc = 0.f;
        #pragma unroll
        for (int k = 0; k < 16; ++k) acc += W[i16 * 16 + k] * U[k * 16 + j16];
        sPS[i16][j16] = acc;
    }
    __syncthreads();
    {
        float acc = 0.f;
        #pragma unroll
        for (int k = 0; k < 16; ++k) acc += sPS[i16][k] * W[j16 * 16 + k];
        sQ[i16][j16] = acc;
    }
    __syncthreads();

    int conv_t = RIC_CAP - 1;

    for (int t = 0; t < RIC_CAP; ++t) {
        const bool chk = ((t & 7) == 7);

        // ---- s1: BS = B*S
        if (tid < 128) {
            float acc = 0.f;
            #pragma unroll
            for (int l = 0; l < 16; ++l) acc += sB[jr][l] * sS[l][cr];
            sBS[jr][cr] = acc;
        }
        __syncthreads();

        // ---- s2: Aug = [B S B^T + V | I], register copy v
        float v = 0.f;
        if (tid < 128) {
            if (cr < 8) {
                float acc = sV[jr][cr];
                #pragma unroll
                for (int k = 0; k < 16; ++k) acc += sBS[jr][k] * sB[cr][k];
                v = acc;
            } else {
                v = (cr - 8 == jr) ? 1.f : 0.f;
            }
            sGJ[jr][cr] = v;
        }
        __syncthreads();

        // ---- s3: unnormalized Gauss-Jordan, 1 barrier per pivot.
        float prod = 1.f;
        #pragma unroll
        for (int k = 0; k < 8; ++k) {
            if (tid < 128) {
                float p    = sGJ[k][k];
                float rowk = sGJ[k][cr];
                float f    = __shfl_sync(0xffffffffu, v, k, 16);  // own row, col k
                if (jr != k) {
                    v = fmaf(-f * __frcp_rn(p), rowk, v);
                    sGJ[jr][cr] = v;
                }
            }
            if (tid == 0) prod *= sGJ[k][k];
            __syncthreads();
        }

        // ---- s4: deferred pivot scale -> inverse; write Minv, logdet
        if (tid < 128 && cr >= 8) {
            float inv = v * __frcp_rn(sGJ[jr][jr]);
            sInv[jr][cr - 8] = inv;
            g_Minv[t * 64 + jr * 8 + (cr - 8)] = inv;
        }
        if (tid == 0) g_logdet[t] = __logf(prod);
        __syncthreads();

        // ---- s5: SBR[i][j] = sum_m BS[m][i] * Inv[m][j]  (S B^T = BS^T)
        if (tid < 128) {
            int i = tid >> 3, j = tid & 7;
            float acc = 0.f;
            #pragma unroll
            for (int m = 0; m < 8; ++m) acc += sBS[m][i] * sInv[m][j];
            sSBR[i][j] = acc;
        }
        __syncthreads();

        // ---- s6: tid<128 -> post_S (2 elems each); tid>=128 -> M table
        if (tid < 128) {
            #pragma unroll
            for (int e = tid; e < 256; e += 128) {
                int i = e >> 4, k = e & 15;
                float acc = sS[i][k];
                #pragma unroll
                for (int j = 0; j < 8; ++j) acc -= sSBR[i][j] * sBS[j][k];
                sPS[i][k] = acc;
            }
        } else {
            int idx = tid - 128;
            int i = idx >> 3, j = idx & 7;
            float acc = 0.f;
            #pragma unroll
            for (int k = 0; k < 16; ++k) acc += sA[i][k] * sSBR[k][j];
            g_M[t * 128 + idx] = acc;
        }
        __syncthreads();

        // ---- s7: AP = A * post_S
        {
            float acc = 0.f;
            #pragma unroll
            for (int l = 0; l < 16; ++l) acc += sA[i16][l] * sPS[l][j16];
            sAP[i16][j16] = acc;
        }
        if (tid == 0 && chk) s_max = 0;
        __syncthreads();

        // ---- s8: Snew = Q + sym(AP*A^T)
        {
            float x1 = 0.f, x2 = 0.f;
            #pragma unroll
            for (int m = 0; m < 16; ++m) {
                x1 += sAP[i16][m] * sA[j16][m];
                x2 += sAP[j16][m] * sA[i16][m];
            }
            float snew = sQ[i16][j16] + 0.5f * (x1 + x2);
            if (chk) {
                float d = fabsf(snew - sS[i16][j16]);
                atomicMax(&s_max, __float_as_int(d));
            }
            sS[i16][j16] = snew;
        }
        __syncthreads();
        if (chk) {
            if (tid == 0 && __int_as_float(s_max) < 3e-5f) s_done = 1;
            __syncthreads();
            if (s_done) { conv_t = t; break; }
        }
    }

    if (tid == 0) g_conv = conv_t;
}

// =====================================================================
// fillG: replicate converged tables to t > g_conv, then build
// G_t = A - M_t*B and atld_t = a - M_t*b for all t.
// =====================================================================
__global__ void __launch_bounds__(256)
fillG_kernel(const float* __restrict__ A, const float* __restrict__ B,
             const float* __restrict__ a, const float* __restrict__ b)
{
    int t = blockIdx.x;
    int tid = threadIdx.x;
    int c = g_conv;
    if (t > c) {
        if (tid < 128) g_M[t * 128 + tid] = g_M[c * 128 + tid];
        if (tid < 64)  g_Minv[t * 64 + tid] = g_Minv[c * 64 + tid];
        if (tid == 0)  g_logdet[t] = g_logdet[c];
        __syncthreads();
    }
    int i = tid >> 4, k = tid & 15;
    const float* Mrow = g_M + t * 128 + i * 8;
    float acc = A[tid];
    #pragma unroll
    for (int j = 0; j < 8; ++j) acc -= Mrow[j] * B[j * 16 + k];
    g_G[t * 256 + tid] = acc;
    if (tid < 16) {
        const float* Mr = g_M + t * 128 + tid * 8;
        float av = a[tid];
        #pragma unroll
        for (int j = 0; j < 8; ++j) av -= Mr[j] * b[j];
        g_atld[t * 16 + tid] = av;
    }
}

// =====================================================================
// Chunk transition products: H_c = G_{15} ... G_0 (reads precomputed G)
// =====================================================================
__global__ void __launch_bounds__(256, 1)
chunkH_kernel()
{
    __shared__ float sH[2][16][16];
    int tid = threadIdx.x;
    int i = tid >> 4, c = tid & 15;
    sH[0][i][c] = (i == c) ? 1.f : 0.f;
    __syncthreads();

    int cur = 0;
    for (int s = 0; s < CHUNKL; ++s) {
        int t = blockIdx.x * CHUNKL + s;
        const float* Gr = g_G + t * 256 + i * 16;
        float acc = 0.f;
        #pragma unroll
        for (int k = 0; k < 16; ++k) acc += Gr[k] * sH[cur][k][c];
        sH[cur ^ 1][i][c] = acc;
        cur ^= 1;
        __syncthreads();
    }
    g_H[blockIdx.x * 256 + tid] = sH[cur][i][c];
}

// ---- depth-4 tree dot helpers -------------------------------------------
__device__ __forceinline__ float dot16_tree(float4 G0, float4 G1, float4 G2,
                                            float4 G3, const float* mu)
{
    float p0 = fmaf(G0.x, mu[0],  G0.y * mu[1]);
    float p1 = fmaf(G0.z, mu[2],  G0.w * mu[3]);
    float p2 = fmaf(G1.x, mu[4],  G1.y * mu[5]);
    float p3 = fmaf(G1.z, mu[6],  G1.w * mu[7]);
    float p4 = fmaf(G2.x, mu[8],  G2.y * mu[9]);
    float p5 = fmaf(G2.z, mu[10], G2.w * mu[11]);
    float p6 = fmaf(G3.x, mu[12], G3.y * mu[13]);
    float p7 = fmaf(G3.z, mu[14], G3.w * mu[15]);
    return ((p0 + p1) + (p2 + p3)) + ((p4 + p5) + (p6 + p7));
}
__device__ __forceinline__ float dot8_tree(float4 m0, float4 m1,
                                           float4 x0, float4 x1)
{
    float q0 = fmaf(m0.x, x0.x, m0.y * x0.y);
    float q1 = fmaf(m0.z, x0.z, m0.w * x0.w);
    float q2 = fmaf(m1.x, x1.x, m1.y * x1.y);
    float q3 = fmaf(m1.z, x1.z, m1.w * x1.w);
    return (q0 + q1) + (q2 + q3);
}

// =====================================================================
// Pass B: zero-init chunk responses (G-form, no innovation on the chain).
// grid = NCHUNK*16 blocks of 256 thr; 16 batches per block.
// =====================================================================
__global__ void __launch_bounds__(256)
passB_kernel(const float* __restrict__ x)
{
    const unsigned FULL = 0xffffffffu;
    int tid = threadIdx.x;
    int lane = tid & 31, warp = tid >> 5;
    int chunk = blockIdx.x >> 4, sub = blockIdx.x & 15;
    int g = lane >> 4, i = lane & 15;
    int batch = sub * 16 + warp * 2 + g;

    float mu[16];
    #pragma unroll
    for (int k = 0; k < 16; ++k) mu[k] = 0.f;
    float own = 0.f;

    const float* xb = x + (size_t)batch * T_LEN * 8;
    int t0 = chunk * CHUNKL;

    for (int s = 0; s < CHUNKL; ++s) {
        int t = t0 + s;
        const float4* Gp = (const float4*)(g_G + t * 256 + i * 16);
        const float4* Mp = (const float4*)(g_M + t * 128 + i * 8);
        const float4* xp = (const float4*)(xb + t * 8);
        float4 G0 = Gp[0], G1 = Gp[1], G2 = Gp[2], G3 = Gp[3];
        float4 m0 = Mp[0], m1 = Mp[1];
        float4 x0 = xp[0], x1 = xp[1];
        float at = g_atld[t * 16 + i];

        float mn = at + dot16_tree(G0, G1, G2, G3, mu) + dot8_tree(m0, m1, x0, x1);
        own = mn;
        #pragma unroll
        for (int k = 0; k < 16; ++k) mu[k] = __shfl_sync(FULL, mn, k, 16);
    }
    g_p[(chunk * NBATCH + batch) * 16 + i] = own;
}

// =====================================================================
// Combine: sequential over 64 chunks, parallel over batches, with
// explicit next-chunk prefetch of H and p.
// =====================================================================
__global__ void __launch_bounds__(32, 1)
combine_kernel(const float* __restrict__ a0)
{
    const unsigned FULL = 0xffffffffu;
    int lane = threadIdx.x;
    int g = lane >> 4, i = lane & 15;
    int batch = blockIdx.x * 2 + g;

    float own = a0[i];
    float mu[16];
    #pragma unroll
    for (int k = 0; k < 16; ++k) mu[k] = __shfl_sync(FULL, own, k, 16);

    float4 h0, h1, h2, h3; float pv;
    {
        const float4* Hp = (const float4*)(g_H + i * 16);
        h0 = Hp[0]; h1 = Hp[1]; h2 = Hp[2]; h3 = Hp[3];
        pv = g_p[batch * 16 + i];
    }

    for (int c = 0; c < NCHUNK; ++c) {
        g_mustart[(c * NBATCH + batch) * 16 + i] = own;
        float mn = pv + dot16_tree(h0, h1, h2, h3, mu);
        if (c + 1 < NCHUNK) {
            const float4* Hp = (const float4*)(g_H + (c + 1) * 256 + i * 16);
            h0 = Hp[0]; h1 = Hp[1]; h2 = Hp[2]; h3 = Hp[3];
            pv = g_p[((c + 1) * NBATCH + batch) * 16 + i];
        }
        own = mn;
        #pragma unroll
        for (int k = 0; k < 16; ++k) mu[k] = __shfl_sync(FULL, mn, k, 16);
    }
}

// =====================================================================
// Pass D: per-chunk NLL from true chunk-entry states. G-form mu update;
// innovation/quad form off the critical path.
// =====================================================================
__global__ void __launch_bounds__(256)
passD_kernel(const float* __restrict__ x, const float* __restrict__ b,
             const float* __restrict__ B)
{
    const unsigned FULL = 0xffffffffu;
    const float LOG2PI = 1.8378770664093453f;
    int tid = threadIdx.x;
    int lane = tid & 31, warp = tid >> 5;
    int chunk = blockIdx.x >> 4, sub = blockIdx.x & 15;
    int g = lane >> 4, i = lane & 15;
    int batch = sub * 16 + warp * 2 + g;

    float Brow[16];
    #pragma unroll
    for (int k = 0; k < 16; ++k) Brow[k] = (i < 8) ? B[i * 16 + k] : 0.f;
    float b_i = (i < 8) ? b[i] : 0.f;

    float mu[16];
    {
        float mi = g_mustart[(chunk * NBATCH + batch) * 16 + i];
        #pragma unroll
        for (int k = 0; k < 16; ++k) mu[k] = __shfl_sync(FULL, mi, k, 16);
    }

    const float* xb = x + (size_t)batch * T_LEN * 8;
    int t0 = chunk * CHUNKL;
    float nll = 0.f;

    for (int s = 0; s < CHUNKL; ++s) {
        int t = t0 + s;
        // --- innovation (side branch) ---
        float xv = (i < 8) ? xb[t * 8 + i] : 0.f;
        float dotB = 0.f;
        {
            float d0 = fmaf(Brow[0], mu[0],  Brow[1] * mu[1]);
            float d1 = fmaf(Brow[2], mu[2],  Brow[3] * mu[3]);
            float d2 = fmaf(Brow[4], mu[4],  Brow[5] * mu[5]);
            float d3 = fmaf(Brow[6], mu[6],  Brow[7] * mu[7]);
            float d4 = fmaf(Brow[8], mu[8],  Brow[9] * mu[9]);
            float d5 = fmaf(Brow[10], mu[10], Brow[11] * mu[11]);
            float d6 = fmaf(Brow[12], mu[12], Brow[13] * mu[13]);
            float d7 = fmaf(Brow[14], mu[14], Brow[15] * mu[15]);
            dotB = ((d0 + d1) + (d2 + d3)) + ((d4 + d5) + (d6 + d7));
        }
        float innov = xv - b_i - dotB;

        float iv0 = __shfl_sync(FULL, innov, 0, 16);
        float iv1 = __shfl_sync(FULL, innov, 1, 16);
        float iv2 = __shfl_sync(FULL, innov, 2, 16);
        float iv3 = __shfl_sync(FULL, innov, 3, 16);
        float iv4 = __shfl_sync(FULL, innov, 4, 16);
        float iv5 = __shfl_sync(FULL, innov, 5, 16);
        float iv6 = __shfl_sync(FULL, innov, 6, 16);
        float iv7 = __shfl_sync(FULL, innov, 7, 16);

        // quad form: lane j<8 contributes innov_j * (Minv innov)_j
        const float4* mp = (const float4*)(g_Minv + t * 64 + (i & 7) * 8);
        float4 n0 = mp[0], n1 = mp[1];
        float qf = n0.x * iv0 + n0.y * iv1 + n0.z * iv2 + n0.w * iv3
                 + n1.x * iv4 + n1.y * iv5 + n1.z * iv6 + n1.w * iv7;
        float sred = (i < 8) ? innov * qf : 0.f;
        #pragma unroll
        for (int off = 1; off < 16; off <<= 1)
            sred += __shfl_xor_sync(FULL, sred, off, 16);

        nll += 0.5f * (sred + g_logdet[t] + 8.f * LOG2PI);

        // --- mu update (critical path, G-form) ---
        const float4* Gp = (const float4*)(g_G + t * 256 + i * 16);
        const float4* Mp = (const float4*)(g_M + t * 128 + i * 8);
        const float4* xp = (const float4*)(xb + t * 8);
        float4 G0 = Gp[0], G1 = Gp[1], G2 = Gp[2], G3 = Gp[3];
        float4 m0 = Mp[0], m1 = Mp[1];
        float4 x0 = xp[0], x1 = xp[1];
        float at = g_atld[t * 16 + i];

        float mn = at + dot16_tree(G0, G1, G2, G3, mu) + dot8_tree(m0, m1, x0, x1);
        #pragma unroll
        for (int k = 0; k < 16; ++k) mu[k] = __shfl_sync(FULL, mn, k, 16);
    }

    if (i == 0) g_partial[chunk * NBATCH + batch] = nll;
}

// =====================================================================
// Reduce: out[b] = sum_c partial[c][b]   (deterministic order)
// =====================================================================
__global__ void __launch_bounds__(256)
reduce_kernel(float* __restrict__ out)
{
    int b = threadIdx.x;
    float s = 0.f;
    #pragma unroll 8
    for (int c = 0; c < NCHUNK; ++c) s += g_partial[c * NBATCH + b];
    out[b] = s;
}

// =====================================================================
// Launcher
// =====================================================================
extern "C" void kernel_launch(void* const* d_in, const int* in_sizes, int n_in,
                              void* d_out, int out_size)
{
    const float* x  = (const float*)d_in[0];
    const float* a  = (const float*)d_in[1];
    const float* b  = (const float*)d_in[2];
    const float* A  = (const float*)d_in[3];
    const float* B  = (const float*)d_in[4];
    const float* U  = (const float*)d_in[5];
    const float* V  = (const float*)d_in[6];
    const float* W  = (const float*)d_in[7];
    const float* a0 = (const float*)d_in[8];
    const float* A0 = (const float*)d_in[9];
    float* out = (float*)d_out;

    riccati_kernel<<<1, 256>>>(A, B, U, V, W, A0);
    fillG_kernel<<<T_LEN, 256>>>(A, B, a, b);
    chunkH_kernel<<<NCHUNK, 256>>>();
    passB_kernel<<<NCHUNK * 16, 256>>>(x);
    combine_kernel<<<NBATCH / 2, 32>>>(a0);
    passD_kernel<<<NCHUNK * 16, 256>>>(x, b, B);
    reduce_kernel<<<1, 256>>>(out);
}

// round 5
// speedup vs baseline: 2.0611x; 1.1500x over previous
#include <cuda_runtime.h>
#include <math.h>

#define T_LEN   1024
#define NBATCH  256
#define NCHUNK  64
#define CHUNKL  16
#define RIC_CAP 512

// ---------------- device scratch (no allocations allowed) ----------------
__device__ __align__(16) float g_M[T_LEN * 128];       // M_t = A*SBR_t, [t][16][8]
__device__ __align__(16) float g_Minv[T_LEN * 64];     // inv(innov_var_t), [t][8][8]
__device__ __align__(16) float g_logdet[T_LEN];        // logdet(innov_var_t)
__device__ __align__(16) float g_G[T_LEN * 256];       // G_t = A - M_t*B, [t][16][16]
__device__ __align__(16) float g_atld[T_LEN * 16];     // atld_t = a - M_t*b
__device__ __align__(16) float g_H[NCHUNK * 256];      // chunk transition 16x16
__device__ __align__(16) float g_p[NCHUNK * NBATCH * 16];        // zero-init chunk response
__device__ __align__(16) float g_mustart[NCHUNK * NBATCH * 16];  // chunk entry states
__device__ __align__(16) float g_partial[NCHUNK * NBATCH];       // per-chunk nll
__device__ int g_conv;                                  // last t actually computed

// =====================================================================
// Phase 1: batch-independent Riccati. Single block, 256 thr.
// 6 barriers/step; 8x8 inversion entirely in warp-0 registers.
// =====================================================================
__global__ void __launch_bounds__(256, 1)
riccati_kernel(const float* __restrict__ A, const float* __restrict__ B,
               const float* __restrict__ U, const float* __restrict__ V,
               const float* __restrict__ W, const float* __restrict__ A0)
{
    __shared__ float sS[16][16];   // current prior covariance
    __shared__ float sBS[8][16];   // B*S
    __shared__ float sInv[8][8];   // inverse of innov_var
    __shared__ float sSBR[16][8];  // S B^T inv
    __shared__ float sPS[16][16];  // post_S (also WU temp)
    __shared__ float sAP[16][16];  // A*post_S
    __shared__ float sA[16][16], sB[8][16], sQ[16][16], sV[8][8];
    __shared__ int s_max;
    __shared__ int s_done;

    const unsigned FULL = 0xffffffffu;
    const int tid = threadIdx.x;
    const int i16 = tid >> 4, j16 = tid & 15;   // 256-thread (i,j)
    const int jr = tid >> 4, cr = tid & 15;     // 128-thread (row, col)

    sA[i16][j16] = A[tid];
    sS[i16][j16] = A0[tid];                     // S0 = A0
    if (tid < 128) sB[tid >> 4][tid & 15] = B[tid];
    if (tid < 64)  sV[tid >> 3][tid & 7]  = V[tid];
    if (tid == 0) s_done = 0;
    __syncthreads();

    // Q = W U W^T  (WU staged in sPS)
    {
        float acc = 0.f;
        #pragma unroll
        for (int k = 0; k < 16; ++k) acc += W[i16 * 16 + k] * U[k * 16 + j16];
        sPS[i16][j16] = acc;
    }
    __syncthreads();
    {
        float acc = 0.f;
        #pragma unroll
        for (int k = 0; k < 16; ++k) acc += sPS[i16][k] * W[j16 * 16 + k];
        sQ[i16][j16] = acc;
    }
    __syncthreads();

    int conv_t = RIC_CAP - 1;

    for (int t = 0; t < RIC_CAP; ++t) {
        const bool chk = ((t & 7) == 7);

        // ---- s1: BS = B*S
        if (tid < 128) {
            float acc = 0.f;
            #pragma unroll
            for (int l = 0; l < 16; ++l) acc += sB[jr][l] * sS[l][cr];
            sBS[jr][cr] = acc;
        }
        __syncthreads();

        // ---- warp 0: build innov_var, invert in registers, logdet.
        // lane layout: j = lane>>2 (row 0..7), cq = lane&3 (col group of 4).
        if (tid < 32) {
            int lane = tid;
            int j = lane >> 2, cq = lane & 3;
            float v[4];
            if (cq < 2) {                       // data cols c = cq*4+r
                #pragma unroll
                for (int r = 0; r < 4; ++r) {
                    int c = cq * 4 + r;
                    float acc = sV[j][c];
                    #pragma unroll
                    for (int k = 0; k < 16; ++k) acc += sBS[j][k] * sB[c][k];
                    v[r] = acc;
                }
            } else {                            // identity cols
                #pragma unroll
                for (int r = 0; r < 4; ++r)
                    v[r] = ((cq - 2) * 4 + r == j) ? 1.f : 0.f;
            }
            // unnormalized Gauss-Jordan, shuffles only
            float prod = 1.f, mydiag = 1.f;
            #pragma unroll
            for (int k = 0; k < 8; ++k) {
                float pk = __shfl_sync(FULL, v[k & 3], (k << 2) | (k >> 2));
                float fk = __shfl_sync(FULL, v[k & 3], (lane & 28) | (k >> 2));
                float r0 = __shfl_sync(FULL, v[0], (k << 2) | cq);
                float r1 = __shfl_sync(FULL, v[1], (k << 2) | cq);
                float r2 = __shfl_sync(FULL, v[2], (k << 2) | cq);
                float r3 = __shfl_sync(FULL, v[3], (k << 2) | cq);
                if (j != k) {
                    float c = fk * __frcp_rn(pk);
                    v[0] = fmaf(-c, r0, v[0]);
                    v[1] = fmaf(-c, r1, v[1]);
                    v[2] = fmaf(-c, r2, v[2]);
                    v[3] = fmaf(-c, r3, v[3]);
                } else {
                    mydiag = pk;
                }
                prod *= pk;
            }
            float rd = __frcp_rn(mydiag);
            if (cq >= 2) {
                #pragma unroll
                for (int r = 0; r < 4; ++r) {
                    int c = (cq - 2) * 4 + r;
                    float iv = v[r] * rd;
                    sInv[j][c] = iv;
                    g_Minv[t * 64 + j * 8 + c] = iv;
                }
            }
            if (lane == 0) g_logdet[t] = __logf(prod);
        }
        __syncthreads();

        // ---- SBR[i][j] = sum_m BS[m][i] * Inv[m][j]  (S B^T = BS^T)
        if (tid < 128) {
            int i = tid >> 3, j = tid & 7;
            float acc = 0.f;
            #pragma unroll
            for (int m = 0; m < 8; ++m) acc += sBS[m][i] * sInv[m][j];
            sSBR[i][j] = acc;
        }
        __syncthreads();

        // ---- tid<128 -> post_S (2 elems each); tid>=128 -> M table
        if (tid < 128) {
            #pragma unroll
            for (int e = tid; e < 256; e += 128) {
                int i = e >> 4, k = e & 15;
                float acc = sS[i][k];
                #pragma unroll
                for (int j = 0; j < 8; ++j) acc -= sSBR[i][j] * sBS[j][k];
                sPS[i][k] = acc;
            }
        } else {
            int idx = tid - 128;
            int i = idx >> 3, j = idx & 7;
            float acc = 0.f;
            #pragma unroll
            for (int k = 0; k < 16; ++k) acc += sA[i][k] * sSBR[k][j];
            g_M[t * 128 + idx] = acc;
        }
        __syncthreads();

        // ---- AP = A * post_S
        {
            float acc = 0.f;
            #pragma unroll
            for (int l = 0; l < 16; ++l) acc += sA[i16][l] * sPS[l][j16];
            sAP[i16][j16] = acc;
        }
        if (tid == 0 && chk) s_max = 0;
        __syncthreads();

        // ---- Snew = Q + sym(AP*A^T)
        {
            float x1 = 0.f, x2 = 0.f;
            #pragma unroll
            for (int m = 0; m < 16; ++m) {
                x1 += sAP[i16][m] * sA[j16][m];
                x2 += sAP[j16][m] * sA[i16][m];
            }
            float snew = sQ[i16][j16] + 0.5f * (x1 + x2);
            if (chk) {
                float d = fabsf(snew - sS[i16][j16]);
                atomicMax(&s_max, __float_as_int(d));
            }
            sS[i16][j16] = snew;
        }
        __syncthreads();
        if (chk) {
            if (tid == 0 && __int_as_float(s_max) < 2e-5f) s_done = 1;
            __syncthreads();
            if (s_done) { conv_t = t; break; }
        }
    }

    if (tid == 0) g_conv = conv_t;
}

// =====================================================================
// prep: per chunk — freeze-fill tables, build G_t / atld_t, and the
// chunk transition product H_c = G_{15}...G_0. One block per chunk.
// =====================================================================
__global__ void __launch_bounds__(256, 1)
prep_kernel(const float* __restrict__ A, const float* __restrict__ B,
            const float* __restrict__ a, const float* __restrict__ b)
{
    __shared__ float sM[16][8];
    __shared__ float sG[16][16];
    __shared__ float sH[2][16][16];
    int tid = threadIdx.x;
    int i = tid >> 4, k = tid & 15;
    int conv = g_conv;

    sH[0][i][k] = (i == k) ? 1.f : 0.f;
    float a_ik = A[tid];
    float Bcol[8];
    #pragma unroll
    for (int j = 0; j < 8; ++j) Bcol[j] = B[j * 16 + k];
    int cur = 0;
    __syncthreads();

    for (int s = 0; s < CHUNKL; ++s) {
        int t = blockIdx.x * CHUNKL + s;
        int src = (t > conv) ? conv : t;
        if (tid < 128) {
            float mv = g_M[src * 128 + tid];
            if (t > conv) g_M[t * 128 + tid] = mv;
            sM[tid >> 3][tid & 7] = mv;
        } else if (tid < 192) {
            int id = tid - 128;
            if (t > conv) g_Minv[t * 64 + id] = g_Minv[conv * 64 + id];
        } else if (tid == 192) {
            if (t > conv) g_logdet[t] = g_logdet[conv];
        }
        __syncthreads();

        float gv = a_ik;
        #pragma unroll
        for (int j = 0; j < 8; ++j) gv -= sM[i][j] * Bcol[j];
        g_G[t * 256 + tid] = gv;
        sG[i][k] = gv;
        if (tid < 16) {
            float av = a[tid];
            #pragma unroll
            for (int j = 0; j < 8; ++j) av -= sM[tid][j] * b[j];
            g_atld[t * 16 + tid] = av;
        }
        __syncthreads();

        float acc = 0.f;
        #pragma unroll
        for (int kk = 0; kk < 16; ++kk) acc += sG[i][kk] * sH[cur][kk][k];
        sH[cur ^ 1][i][k] = acc;
        cur ^= 1;
        __syncthreads();
    }
    g_H[blockIdx.x * 256 + tid] = sH[cur][i][k];
}

// ---- depth-4 tree dot helpers -------------------------------------------
__device__ __forceinline__ float dot16_tree(float4 G0, float4 G1, float4 G2,
                                            float4 G3, const float* mu)
{
    float p0 = fmaf(G0.x, mu[0],  G0.y * mu[1]);
    float p1 = fmaf(G0.z, mu[2],  G0.w * mu[3]);
    float p2 = fmaf(G1.x, mu[4],  G1.y * mu[5]);
    float p3 = fmaf(G1.z, mu[6],  G1.w * mu[7]);
    float p4 = fmaf(G2.x, mu[8],  G2.y * mu[9]);
    float p5 = fmaf(G2.z, mu[10], G2.w * mu[11]);
    float p6 = fmaf(G3.x, mu[12], G3.y * mu[13]);
    float p7 = fmaf(G3.z, mu[14], G3.w * mu[15]);
    return ((p0 + p1) + (p2 + p3)) + ((p4 + p5) + (p6 + p7));
}
__device__ __forceinline__ float dot8_tree(float4 m0, float4 m1,
                                           float4 x0, float4 x1)
{
    float q0 = fmaf(m0.x, x0.x, m0.y * x0.y);
    float q1 = fmaf(m0.z, x0.z, m0.w * x0.w);
    float q2 = fmaf(m1.x, x1.x, m1.y * x1.y);
    float q3 = fmaf(m1.z, x1.z, m1.w * x1.w);
    return (q0 + q1) + (q2 + q3);
}

// =====================================================================
// Pass B: zero-init chunk responses. 2 batches per lane (table loads
// amortized). grid = NCHUNK*16 blocks of 128 thr; 16 batches per block.
// =====================================================================
__global__ void __launch_bounds__(128)
passB_kernel(const float* __restrict__ x)
{
    const unsigned FULL = 0xffffffffu;
    int tid = threadIdx.x;
    int lane = tid & 31, warp = tid >> 5;
    int chunk = blockIdx.x >> 4, sub = blockIdx.x & 15;
    int g = lane >> 4, i = lane & 15;
    int b0 = sub * 16 + warp * 4 + g * 2;   // this lane's batches: b0, b0+1

    float mu0[16], mu1[16];
    #pragma unroll
    for (int k = 0; k < 16; ++k) { mu0[k] = 0.f; mu1[k] = 0.f; }
    float own0 = 0.f, own1 = 0.f;

    const float* xb0 = x + (size_t)b0 * T_LEN * 8;
    const float* xb1 = xb0 + T_LEN * 8;
    int t0 = chunk * CHUNKL;

    for (int s = 0; s < CHUNKL; ++s) {
        int t = t0 + s;
        const float4* Gp = (const float4*)(g_G + t * 256 + i * 16);
        const float4* Mp = (const float4*)(g_M + t * 128 + i * 8);
        float4 G0 = Gp[0], G1 = Gp[1], G2 = Gp[2], G3 = Gp[3];
        float4 m0 = Mp[0], m1 = Mp[1];
        float at = g_atld[t * 16 + i];
        const float4* xpa = (const float4*)(xb0 + t * 8);
        const float4* xpb = (const float4*)(xb1 + t * 8);
        float4 x0a = xpa[0], x1a = xpa[1];
        float4 x0b = xpb[0], x1b = xpb[1];

        float mn0 = at + dot16_tree(G0, G1, G2, G3, mu0) + dot8_tree(m0, m1, x0a, x1a);
        float mn1 = at + dot16_tree(G0, G1, G2, G3, mu1) + dot8_tree(m0, m1, x0b, x1b);
        own0 = mn0; own1 = mn1;
        #pragma unroll
        for (int k = 0; k < 16; ++k) {
            mu0[k] = __shfl_sync(FULL, mn0, k, 16);
            mu1[k] = __shfl_sync(FULL, mn1, k, 16);
        }
    }
    g_p[(chunk * NBATCH + b0)     * 16 + i] = own0;
    g_p[(chunk * NBATCH + b0 + 1) * 16 + i] = own1;
}

// =====================================================================
// Combine: sequential over 64 chunks, parallel over batches, with
// explicit next-chunk prefetch of H and p.
// =====================================================================
__global__ void __launch_bounds__(32, 1)
combine_kernel(const float* __restrict__ a0)
{
    const unsigned FULL = 0xffffffffu;
    int lane = threadIdx.x;
    int g = lane >> 4, i = lane & 15;
    int batch = blockIdx.x * 2 + g;

    float own = a0[i];
    float mu[16];
    #pragma unroll
    for (int k = 0; k < 16; ++k) mu[k] = __shfl_sync(FULL, own, k, 16);

    float4 h0, h1, h2, h3; float pv;
    {
        const float4* Hp = (const float4*)(g_H + i * 16);
        h0 = Hp[0]; h1 = Hp[1]; h2 = Hp[2]; h3 = Hp[3];
        pv = g_p[batch * 16 + i];
    }

    for (int c = 0; c < NCHUNK; ++c) {
        g_mustart[(c * NBATCH + batch) * 16 + i] = own;
        float mn = pv + dot16_tree(h0, h1, h2, h3, mu);
        if (c + 1 < NCHUNK) {
            const float4* Hp = (const float4*)(g_H + (c + 1) * 256 + i * 16);
            h0 = Hp[0]; h1 = Hp[1]; h2 = Hp[2]; h3 = Hp[3];
            pv = g_p[((c + 1) * NBATCH + batch) * 16 + i];
        }
        own = mn;
        #pragma unroll
        for (int k = 0; k < 16; ++k) mu[k] = __shfl_sync(FULL, mn, k, 16);
    }
}

// =====================================================================
// Pass D: per-chunk NLL from true chunk-entry states. 2 batches/lane;
// quad-form lane-reduction deferred out of the step loop.
// =====================================================================
__global__ void __launch_bounds__(128)
passD_kernel(const float* __restrict__ x, const float* __restrict__ b,
             const float* __restrict__ B)
{
    const unsigned FULL = 0xffffffffu;
    const float LOG2PI = 1.8378770664093453f;
    int tid = threadIdx.x;
    int lane = tid & 31, warp = tid >> 5;
    int chunk = blockIdx.x >> 4, sub = blockIdx.x & 15;
    int g = lane >> 4, i = lane & 15;
    int b0 = sub * 16 + warp * 4 + g * 2;

    float Brow[16];
    #pragma unroll
    for (int k = 0; k < 16; ++k) Brow[k] = (i < 8) ? B[i * 16 + k] : 0.f;
    float b_i = (i < 8) ? b[i] : 0.f;

    float mu0[16], mu1[16];
    {
        float m0s = g_mustart[(chunk * NBATCH + b0)     * 16 + i];
        float m1s = g_mustart[(chunk * NBATCH + b0 + 1) * 16 + i];
        #pragma unroll
        for (int k = 0; k < 16; ++k) {
            mu0[k] = __shfl_sync(FULL, m0s, k, 16);
            mu1[k] = __shfl_sync(FULL, m1s, k, 16);
        }
    }

    const float* xb0 = x + (size_t)b0 * T_LEN * 8;
    const float* xb1 = xb0 + T_LEN * 8;
    int t0 = chunk * CHUNKL;
    float sred0 = 0.f, sred1 = 0.f, ldsum = 0.f;

    for (int s = 0; s < CHUNKL; ++s) {
        int t = t0 + s;
        // innovation component (lanes 0..7 meaningful)
        float xv0 = (i < 8) ? xb0[t * 8 + i] : 0.f;
        float xv1 = (i < 8) ? xb1[t * 8 + i] : 0.f;
        float innov0 = xv0 - b_i - dot16_tree(*(const float4*)(Brow),
                                              *(const float4*)(Brow + 4),
                                              *(const float4*)(Brow + 8),
                                              *(const float4*)(Brow + 12), mu0);
        float innov1 = xv1 - b_i - dot16_tree(*(const float4*)(Brow),
                                              *(const float4*)(Brow + 4),
                                              *(const float4*)(Brow + 8),
                                              *(const float4*)(Brow + 12), mu1);

        float iva[8], ivb[8];
        #pragma unroll
        for (int j = 0; j < 8; ++j) {
            iva[j] = __shfl_sync(FULL, innov0, j, 16);
            ivb[j] = __shfl_sync(FULL, innov1, j, 16);
        }

        const float4* mp = (const float4*)(g_Minv + t * 64 + (i & 7) * 8);
        float4 n0 = mp[0], n1 = mp[1];
        float qf0 = n0.x * iva[0] + n0.y * iva[1] + n0.z * iva[2] + n0.w * iva[3]
                  + n1.x * iva[4] + n1.y * iva[5] + n1.z * iva[6] + n1.w * iva[7];
        float qf1 = n0.x * ivb[0] + n0.y * ivb[1] + n0.z * ivb[2] + n0.w * ivb[3]
                  + n1.x * ivb[4] + n1.y * ivb[5] + n1.z * ivb[6] + n1.w * ivb[7];
        sred0 += (i < 8) ? innov0 * qf0 : 0.f;
        sred1 += (i < 8) ? innov1 * qf1 : 0.f;
        ldsum += g_logdet[t];

        // mu update (G-form)
        const float4* Gp = (const float4*)(g_G + t * 256 + i * 16);
        const float4* Mp = (const float4*)(g_M + t * 128 + i * 8);
        float4 G0 = Gp[0], G1 = Gp[1], G2 = Gp[2], G3 = Gp[3];
        float4 m0 = Mp[0], m1 = Mp[1];
        float at = g_atld[t * 16 + i];
        const float4* xpa = (const float4*)(xb0 + t * 8);
        const float4* xpb = (const float4*)(xb1 + t * 8);
        float4 x0a = xpa[0], x1a = xpa[1];
        float4 x0b = xpb[0], x1b = xpb[1];

        float mn0 = at + dot16_tree(G0, G1, G2, G3, mu0) + dot8_tree(m0, m1, x0a, x1a);
        float mn1 = at + dot16_tree(G0, G1, G2, G3, mu1) + dot8_tree(m0, m1, x0b, x1b);
        #pragma unroll
        for (int k = 0; k < 16; ++k) {
            mu0[k] = __shfl_sync(FULL, mn0, k, 16);
            mu1[k] = __shfl_sync(FULL, mn1, k, 16);
        }
    }

    // deferred lane reduction (lanes 8..15 carry zeros)
    #pragma unroll
    for (int off = 1; off < 16; off <<= 1) {
        sred0 += __shfl_xor_sync(FULL, sred0, off, 16);
        sred1 += __shfl_xor_sync(FULL, sred1, off, 16);
    }
    if (i == 0) {
        float base = ldsum + (float)CHUNKL * 8.f * LOG2PI;
        g_partial[chunk * NBATCH + b0]     = 0.5f * (sred0 + base);
        g_partial[chunk * NBATCH + b0 + 1] = 0.5f * (sred1 + base);
    }
}

// =====================================================================
// Reduce: out[b] = sum_c partial[c][b]   (deterministic order)
// =====================================================================
__global__ void __launch_bounds__(256)
reduce_kernel(float* __restrict__ out)
{
    int b = threadIdx.x;
    float s = 0.f;
    #pragma unroll 8
    for (int c = 0; c < NCHUNK; ++c) s += g_partial[c * NBATCH + b];
    out[b] = s;
}

// =====================================================================
// Launcher
// =====================================================================
extern "C" void kernel_launch(void* const* d_in, const int* in_sizes, int n_in,
                              void* d_out, int out_size)
{
    const float* x  = (const float*)d_in[0];
    const float* a  = (const float*)d_in[1];
    const float* b  = (const float*)d_in[2];
    const float* A  = (const float*)d_in[3];
    const float* B  = (const float*)d_in[4];
    const float* U  = (const float*)d_in[5];
    const float* V  = (const float*)d_in[6];
    const float* W  = (const float*)d_in[7];
    const float* a0 = (const float*)d_in[8];
    const float* A0 = (const float*)d_in[9];
    float* out = (float*)d_out;

    riccati_kernel<<<1, 256>>>(A, B, U, V, W, A0);
    prep_kernel<<<NCHUNK, 256>>>(A, B, a, b);
    passB_kernel<<<NCHUNK * 16, 128>>>(x);
    combine_kernel<<<NBATCH / 2, 32>>>(a0);
    passD_kernel<<<NCHUNK * 16, 128>>>(x, b, B);
    reduce_kernel<<<1, 256>>>(out);
}

// round 6
// speedup vs baseline: 2.4989x; 1.2124x over previous
#include <cuda_runtime.h>
#include <math.h>

#define T_LEN   1024
#define NBATCH  256
#define NCHUNK  64
#define CHUNKL  16
#define RIC_CAP 512

// ---------------- device scratch (no allocations allowed) ----------------
__device__ __align__(16) float g_M[T_LEN * 128];       // M_t = A*SBR_t, [t][16][8]
__device__ __align__(16) float g_Minv[T_LEN * 64];     // inv(innov_var_t), [t][8][8]
__device__ __align__(16) float g_logdet[T_LEN];        // logdet(innov_var_t)
__device__ __align__(16) float g_G[T_LEN * 256];       // G_t = A - M_t*B, [t][16][16]
__device__ __align__(16) float g_atld[T_LEN * 16];     // atld_t = a - M_t*b
__device__ __align__(16) float g_H[NCHUNK * 256];      // chunk transition 16x16
__device__ __align__(16) float g_p[NCHUNK * NBATCH * 16];        // zero-init chunk response
__device__ __align__(16) float g_mustart[NCHUNK * NBATCH * 16];  // chunk entry states
__device__ __align__(16) float g_partial[NCHUNK * NBATCH];       // per-chunk nll
__device__ int g_conv;                                  // last t actually computed

// =====================================================================
// Phase 1: batch-independent Riccati. Single block, 256 thr.
// 5 barriers/step. Snew = AS*A^T + Q - M*P^T with P = A*S*B^T, M = P*Rinv.
// 8x8 inversion in warp-0 registers, overlapped with ASA compute.
// Convergence freeze on max|dM| < 1e-5, checked every 4 steps.
// =====================================================================
__global__ void __launch_bounds__(256, 1)
riccati_kernel(const float* __restrict__ A, const float* __restrict__ B,
               const float* __restrict__ U, const float* __restrict__ V,
               const float* __restrict__ W, const float* __restrict__ A0)
{
    __shared__ float sS[16][16];     // current prior covariance
    __shared__ float sAS[16][16];    // A*S
    __shared__ float sSBt[16][8];    // S*B^T
    __shared__ float sR[8][8];       // innov_var
    __shared__ float sInv[8][8];     // inverse of innov_var
    __shared__ float sP[16][8];      // A*S*B^T
    __shared__ float sASA[16][16];   // A*S*A^T + Q
    __shared__ float sM[16][8];      // M table entry
    __shared__ float sMprev[16][8];  // previous M (freeze metric)
    __shared__ float sA[16][16], sB[8][16], sQ[16][16], sV[8][8];
    __shared__ int s_max;
    __shared__ int s_done;

    const unsigned FULL = 0xffffffffu;
    const int tid = threadIdx.x;
    const int i16 = tid >> 4, j16 = tid & 15;   // 256-thread (i,j)

    sA[i16][j16] = A[tid];
    sS[i16][j16] = A0[tid];                     // S0 = A0
    if (tid < 128) { sB[tid >> 4][tid & 15] = B[tid]; sMprev[tid >> 3][tid & 7] = 0.f; }
    if (tid < 64)  sV[tid >> 3][tid & 7]  = V[tid];
    if (tid == 0) { s_done = 0; s_max = 0; }
    __syncthreads();

    // Q = W U W^T  (WU staged in sAS)
    {
        float acc = 0.f;
        #pragma unroll
        for (int k = 0; k < 16; ++k) acc += W[i16 * 16 + k] * U[k * 16 + j16];
        sAS[i16][j16] = acc;
    }
    __syncthreads();
    {
        float acc = 0.f;
        #pragma unroll
        for (int k = 0; k < 16; ++k) acc += sAS[i16][k] * W[j16 * 16 + k];
        sQ[i16][j16] = acc;
    }
    __syncthreads();

    int conv_t = RIC_CAP - 1;

    for (int t = 0; t < RIC_CAP; ++t) {
        const bool chk = ((t & 3) == 3);

        // ---- st1: AS = A*S (all), SBt = S*B^T (tid<128)
        {
            float acc = 0.f;
            #pragma unroll
            for (int k = 0; k < 16; ++k) acc += sA[i16][k] * sS[k][j16];
            sAS[i16][j16] = acc;
        }
        if (tid < 128) {
            int i = tid >> 3, j = tid & 7;
            float acc = 0.f;
            #pragma unroll
            for (int k = 0; k < 16; ++k) acc += sS[i][k] * sB[j][k];
            sSBt[i][j] = acc;
        }
        __syncthreads();

        // ---- st2: R = B*SBt + V (tid<64); P = A*SBt (tid 64..191);
        //           first 64 ASA elems (tid 192..255)
        if (tid < 64) {
            int i = tid >> 3, j = tid & 7;
            float acc = sV[i][j];
            #pragma unroll
            for (int k = 0; k < 16; ++k) acc += sB[i][k] * sSBt[k][j];
            sR[i][j] = acc;
        } else if (tid < 192) {
            int id = tid - 64;
            int i = id >> 3, j = id & 7;
            float acc = 0.f;
            #pragma unroll
            for (int k = 0; k < 16; ++k) acc += sA[i][k] * sSBt[k][j];
            sP[i][j] = acc;
        } else {
            int id = tid - 192;            // ASA tasks 0..63
            int i = id >> 4, j = id & 15;
            float acc = sQ[i][j];
            #pragma unroll
            for (int k = 0; k < 16; ++k) acc += sAS[i][k] * sA[j][k];
            sASA[i][j] = acc;
            if (tid == 255 && chk) s_max = 0;
        }
        __syncthreads();

        // ---- st3: warp0 inverts R in registers; others finish ASA
        if (tid < 32) {
            int lane = tid;
            int j = lane >> 2, cq = lane & 3;
            float v[4];
            if (cq < 2) {
                #pragma unroll
                for (int r = 0; r < 4; ++r) v[r] = sR[j][cq * 4 + r];
            } else {
                #pragma unroll
                for (int r = 0; r < 4; ++r)
                    v[r] = ((cq - 2) * 4 + r == j) ? 1.f : 0.f;
            }
            float prod = 1.f, mydiag = 1.f;
            #pragma unroll
            for (int k = 0; k < 8; ++k) {
                float pk = __shfl_sync(FULL, v[k & 3], (k << 2) | (k >> 2));
                float fk = __shfl_sync(FULL, v[k & 3], (lane & 28) | (k >> 2));
                float r0 = __shfl_sync(FULL, v[0], (k << 2) | cq);
                float r1 = __shfl_sync(FULL, v[1], (k << 2) | cq);
                float r2 = __shfl_sync(FULL, v[2], (k << 2) | cq);
                float r3 = __shfl_sync(FULL, v[3], (k << 2) | cq);
                if (j != k) {
                    float c = fk * __frcp_rn(pk);
                    v[0] = fmaf(-c, r0, v[0]);
                    v[1] = fmaf(-c, r1, v[1]);
                    v[2] = fmaf(-c, r2, v[2]);
                    v[3] = fmaf(-c, r3, v[3]);
                } else {
                    mydiag = pk;
                }
                prod *= pk;
            }
            float rd = __frcp_rn(mydiag);
            if (cq >= 2) {
                #pragma unroll
                for (int r = 0; r < 4; ++r) {
                    int c = (cq - 2) * 4 + r;
                    float iv = v[r] * rd;
                    sInv[j][c] = iv;
                    g_Minv[t * 64 + j * 8 + c] = iv;
                }
            }
            if (lane == 0) g_logdet[t] = __logf(prod);
        } else if (tid < 224) {
            int id = tid + 32;             // ASA tasks 64..255
            int i = id >> 4, j = id & 15;
            float acc = sQ[i][j];
            #pragma unroll
            for (int k = 0; k < 16; ++k) acc += sAS[i][k] * sA[j][k];
            sASA[i][j] = acc;
        }
        __syncthreads();

        // ---- st4: M = P*Inv, write table, freeze metric
        if (tid < 128) {
            int i = tid >> 3, j = tid & 7;
            float acc = 0.f;
            #pragma unroll
            for (int m = 0; m < 8; ++m) acc += sP[i][m] * sInv[m][j];
            g_M[t * 128 + tid] = acc;
            sM[i][j] = acc;
            if (chk) {
                float d = fabsf(acc - sMprev[i][j]);
                atomicMax(&s_max, __float_as_int(d));
            }
            sMprev[i][j] = acc;
        }
        __syncthreads();

        // ---- st5: Snew = sym(ASA) - sym(M*P^T)
        {
            float x1 = 0.f, x2 = 0.f;
            #pragma unroll
            for (int m = 0; m < 8; ++m) {
                x1 += sM[i16][m] * sP[j16][m];
                x2 += sM[j16][m] * sP[i16][m];
            }
            sS[i16][j16] = 0.5f * (sASA[i16][j16] + sASA[j16][i16])
                         - 0.5f * (x1 + x2);
        }
        if (tid == 0 && chk && __int_as_float(s_max) < 1e-5f) s_done = 1;
        __syncthreads();
        if (chk && s_done) { conv_t = t; break; }
    }

    if (tid == 0) g_conv = conv_t;
}

// =====================================================================
// prep: per chunk — freeze-fill tables, build G_t / atld_t, and the
// chunk transition product H_c = G_{15}...G_0. One block per chunk.
// =====================================================================
__global__ void __launch_bounds__(256, 1)
prep_kernel(const float* __restrict__ A, const float* __restrict__ B,
            const float* __restrict__ a, const float* __restrict__ b)
{
    __shared__ float sM[16][8];
    __shared__ float sG[16][16];
    __shared__ float sH[2][16][16];
    int tid = threadIdx.x;
    int i = tid >> 4, k = tid & 15;
    int conv = g_conv;

    sH[0][i][k] = (i == k) ? 1.f : 0.f;
    float a_ik = A[tid];
    float Bcol[8];
    #pragma unroll
    for (int j = 0; j < 8; ++j) Bcol[j] = B[j * 16 + k];
    int cur = 0;
    __syncthreads();

    for (int s = 0; s < CHUNKL; ++s) {
        int t = blockIdx.x * CHUNKL + s;
        int src = (t > conv) ? conv : t;
        if (tid < 128) {
            float mv = g_M[src * 128 + tid];
            if (t > conv) g_M[t * 128 + tid] = mv;
            sM[tid >> 3][tid & 7] = mv;
        } else if (tid < 192) {
            int id = tid - 128;
            if (t > conv) g_Minv[t * 64 + id] = g_Minv[conv * 64 + id];
        } else if (tid == 192) {
            if (t > conv) g_logdet[t] = g_logdet[conv];
        }
        __syncthreads();

        float gv = a_ik;
        #pragma unroll
        for (int j = 0; j < 8; ++j) gv -= sM[i][j] * Bcol[j];
        g_G[t * 256 + tid] = gv;
        sG[i][k] = gv;
        if (tid < 16) {
            float av = a[tid];
            #pragma unroll
            for (int j = 0; j < 8; ++j) av -= sM[tid][j] * b[j];
            g_atld[t * 16 + tid] = av;
        }
        __syncthreads();

        float acc = 0.f;
        #pragma unroll
        for (int kk = 0; kk < 16; ++kk) acc += sG[i][kk] * sH[cur][kk][k];
        sH[cur ^ 1][i][k] = acc;
        cur ^= 1;
        __syncthreads();
    }
    g_H[blockIdx.x * 256 + tid] = sH[cur][i][k];
}

// ---- depth-4 tree dot helpers -------------------------------------------
__device__ __forceinline__ float dot16_tree(float4 G0, float4 G1, float4 G2,
                                            float4 G3, const float* mu)
{
    float p0 = fmaf(G0.x, mu[0],  G0.y * mu[1]);
    float p1 = fmaf(G0.z, mu[2],  G0.w * mu[3]);
    float p2 = fmaf(G1.x, mu[4],  G1.y * mu[5]);
    float p3 = fmaf(G1.z, mu[6],  G1.w * mu[7]);
    float p4 = fmaf(G2.x, mu[8],  G2.y * mu[9]);
    float p5 = fmaf(G2.z, mu[10], G2.w * mu[11]);
    float p6 = fmaf(G3.x, mu[12], G3.y * mu[13]);
    float p7 = fmaf(G3.z, mu[14], G3.w * mu[15]);
    return ((p0 + p1) + (p2 + p3)) + ((p4 + p5) + (p6 + p7));
}
__device__ __forceinline__ float dot8_tree(float4 m0, float4 m1,
                                           float4 x0, float4 x1)
{
    float q0 = fmaf(m0.x, x0.x, m0.y * x0.y);
    float q1 = fmaf(m0.z, x0.z, m0.w * x0.w);
    float q2 = fmaf(m1.x, x1.x, m1.y * x1.y);
    float q3 = fmaf(m1.z, x1.z, m1.w * x1.w);
    return (q0 + q1) + (q2 + q3);
}

// =====================================================================
// Pass B: zero-init chunk responses. 2 batches per lane.
// =====================================================================
__global__ void __launch_bounds__(128)
passB_kernel(const float* __restrict__ x)
{
    const unsigned FULL = 0xffffffffu;
    int tid = threadIdx.x;
    int lane = tid & 31, warp = tid >> 5;
    int chunk = blockIdx.x >> 4, sub = blockIdx.x & 15;
    int g = lane >> 4, i = lane & 15;
    int b0 = sub * 16 + warp * 4 + g * 2;

    float mu0[16], mu1[16];
    #pragma unroll
    for (int k = 0; k < 16; ++k) { mu0[k] = 0.f; mu1[k] = 0.f; }
    float own0 = 0.f, own1 = 0.f;

    const float* xb0 = x + (size_t)b0 * T_LEN * 8;
    const float* xb1 = xb0 + T_LEN * 8;
    int t0 = chunk * CHUNKL;

    for (int s = 0; s < CHUNKL; ++s) {
        int t = t0 + s;
        const float4* Gp = (const float4*)(g_G + t * 256 + i * 16);
        const float4* Mp = (const float4*)(g_M + t * 128 + i * 8);
        float4 G0 = Gp[0], G1 = Gp[1], G2 = Gp[2], G3 = Gp[3];
        float4 m0 = Mp[0], m1 = Mp[1];
        float at = g_atld[t * 16 + i];
        const float4* xpa = (const float4*)(xb0 + t * 8);
        const float4* xpb = (const float4*)(xb1 + t * 8);
        float4 x0a = xpa[0], x1a = xpa[1];
        float4 x0b = xpb[0], x1b = xpb[1];

        float mn0 = at + dot16_tree(G0, G1, G2, G3, mu0) + dot8_tree(m0, m1, x0a, x1a);
        float mn1 = at + dot16_tree(G0, G1, G2, G3, mu1) + dot8_tree(m0, m1, x0b, x1b);
        own0 = mn0; own1 = mn1;
        #pragma unroll
        for (int k = 0; k < 16; ++k) {
            mu0[k] = __shfl_sync(FULL, mn0, k, 16);
            mu1[k] = __shfl_sync(FULL, mn1, k, 16);
        }
    }
    g_p[(chunk * NBATCH + b0)     * 16 + i] = own0;
    g_p[(chunk * NBATCH + b0 + 1) * 16 + i] = own1;
}

// =====================================================================
// Combine: 16 blocks x 256 thr (16 batches/block). H staged through
// smem in 16-chunk phases; p prefetched 16-deep into registers.
// =====================================================================
__global__ void __launch_bounds__(256, 1)
combine_kernel(const float* __restrict__ a0)
{
    __shared__ float sHbuf[CHUNKL * 256];   // 16 chunks of H, 16 KB
    const unsigned FULL = 0xffffffffu;
    int tid = threadIdx.x;
    int lane = tid & 31, warp = tid >> 5;
    int g = lane >> 4, i = lane & 15;
    int batch = blockIdx.x * 16 + warp * 2 + g;

    float own = a0[i];
    float mu[16];
    #pragma unroll
    for (int k = 0; k < 16; ++k) mu[k] = __shfl_sync(FULL, own, k, 16);

    for (int ph = 0; ph < NCHUNK / CHUNKL; ++ph) {
        // prefetch p for the whole phase (independent of smem)
        float pv[CHUNKL];
        #pragma unroll
        for (int s = 0; s < CHUNKL; ++s)
            pv[s] = g_p[((ph * CHUNKL + s) * NBATCH + batch) * 16 + i];

        __syncthreads();   // previous phase fully consumed
        {
            const float4* src = (const float4*)(g_H + ph * CHUNKL * 256);
            float4* dst = (float4*)sHbuf;
            #pragma unroll
            for (int q = 0; q < 4; ++q)
                dst[tid + q * 256] = src[tid + q * 256];
        }
        __syncthreads();

        #pragma unroll
        for (int s = 0; s < CHUNKL; ++s) {
            int c = ph * CHUNKL + s;
            g_mustart[(c * NBATCH + batch) * 16 + i] = own;
            const float4* Hp = (const float4*)(sHbuf + s * 256 + i * 16);
            float4 h0 = Hp[0], h1 = Hp[1], h2 = Hp[2], h3 = Hp[3];
            float mn = pv[s] + dot16_tree(h0, h1, h2, h3, mu);
            own = mn;
            #pragma unroll
            for (int k = 0; k < 16; ++k) mu[k] = __shfl_sync(FULL, mn, k, 16);
        }
    }
}

// =====================================================================
// Pass D: per-chunk NLL from true chunk-entry states. 2 batches/lane;
// quad-form lane-reduction deferred out of the step loop.
// =====================================================================
__global__ void __launch_bounds__(128)
passD_kernel(const float* __restrict__ x, const float* __restrict__ b,
             const float* __restrict__ B)
{
    const unsigned FULL = 0xffffffffu;
    const float LOG2PI = 1.8378770664093453f;
    int tid = threadIdx.x;
    int lane = tid & 31, warp = tid >> 5;
    int chunk = blockIdx.x >> 4, sub = blockIdx.x & 15;
    int g = lane >> 4, i = lane & 15;
    int b0 = sub * 16 + warp * 4 + g * 2;

    float Brow[16];
    #pragma unroll
    for (int k = 0; k < 16; ++k) Brow[k] = (i < 8) ? B[i * 16 + k] : 0.f;
    float b_i = (i < 8) ? b[i] : 0.f;

    float mu0[16], mu1[16];
    {
        float m0s = g_mustart[(chunk * NBATCH + b0)     * 16 + i];
        float m1s = g_mustart[(chunk * NBATCH + b0 + 1) * 16 + i];
        #pragma unroll
        for (int k = 0; k < 16; ++k) {
            mu0[k] = __shfl_sync(FULL, m0s, k, 16);
            mu1[k] = __shfl_sync(FULL, m1s, k, 16);
        }
    }

    const float* xb0 = x + (size_t)b0 * T_LEN * 8;
    const float* xb1 = xb0 + T_LEN * 8;
    int t0 = chunk * CHUNKL;
    float sred0 = 0.f, sred1 = 0.f, ldsum = 0.f;

    for (int s = 0; s < CHUNKL; ++s) {
        int t = t0 + s;
        float xv0 = (i < 8) ? xb0[t * 8 + i] : 0.f;
        float xv1 = (i < 8) ? xb1[t * 8 + i] : 0.f;
        float innov0 = xv0 - b_i - dot16_tree(*(const float4*)(Brow),
                                              *(const float4*)(Brow + 4),
                                              *(const float4*)(Brow + 8),
                                              *(const float4*)(Brow + 12), mu0);
        float innov1 = xv1 - b_i - dot16_tree(*(const float4*)(Brow),
                                              *(const float4*)(Brow + 4),
                                              *(const float4*)(Brow + 8),
                                              *(const float4*)(Brow + 12), mu1);

        float iva[8], ivb[8];
        #pragma unroll
        for (int j = 0; j < 8; ++j) {
            iva[j] = __shfl_sync(FULL, innov0, j, 16);
            ivb[j] = __shfl_sync(FULL, innov1, j, 16);
        }

        const float4* mp = (const float4*)(g_Minv + t * 64 + (i & 7) * 8);
        float4 n0 = mp[0], n1 = mp[1];
        float qf0 = n0.x * iva[0] + n0.y * iva[1] + n0.z * iva[2] + n0.w * iva[3]
                  + n1.x * iva[4] + n1.y * iva[5] + n1.z * iva[6] + n1.w * iva[7];
        float qf1 = n0.x * ivb[0] + n0.y * ivb[1] + n0.z * ivb[2] + n0.w * ivb[3]
                  + n1.x * ivb[4] + n1.y * ivb[5] + n1.z * ivb[6] + n1.w * ivb[7];
        sred0 += (i < 8) ? innov0 * qf0 : 0.f;
        sred1 += (i < 8) ? innov1 * qf1 : 0.f;
        ldsum += g_logdet[t];

        const float4* Gp = (const float4*)(g_G + t * 256 + i * 16);
        const float4* Mp = (const float4*)(g_M + t * 128 + i * 8);
        float4 G0 = Gp[0], G1 = Gp[1], G2 = Gp[2], G3 = Gp[3];
        float4 m0 = Mp[0], m1 = Mp[1];
        float at = g_atld[t * 16 + i];
        const float4* xpa = (const float4*)(xb0 + t * 8);
        const float4* xpb = (const float4*)(xb1 + t * 8);
        float4 x0a = xpa[0], x1a = xpa[1];
        float4 x0b = xpb[0], x1b = xpb[1];

        float mn0 = at + dot16_tree(G0, G1, G2, G3, mu0) + dot8_tree(m0, m1, x0a, x1a);
        float mn1 = at + dot16_tree(G0, G1, G2, G3, mu1) + dot8_tree(m0, m1, x0b, x1b);
        #pragma unroll
        for (int k = 0; k < 16; ++k) {
            mu0[k] = __shfl_sync(FULL, mn0, k, 16);
            mu1[k] = __shfl_sync(FULL, mn1, k, 16);
        }
    }

    #pragma unroll
    for (int off = 1; off < 16; off <<= 1) {
        sred0 += __shfl_xor_sync(FULL, sred0, off, 16);
        sred1 += __shfl_xor_sync(FULL, sred1, off, 16);
    }
    if (i == 0) {
        float base = ldsum + (float)CHUNKL * 8.f * LOG2PI;
        g_partial[chunk * NBATCH + b0]     = 0.5f * (sred0 + base);
        g_partial[chunk * NBATCH + b0 + 1] = 0.5f * (sred1 + base);
    }
}

// =====================================================================
// Reduce: out[b] = sum_c partial[c][b]   (deterministic order)
// =====================================================================
__global__ void __launch_bounds__(256)
reduce_kernel(float* __restrict__ out)
{
    int b = threadIdx.x;
    float s = 0.f;
    #pragma unroll 8
    for (int c = 0; c < NCHUNK; ++c) s += g_partial[c * NBATCH + b];
    out[b] = s;
}

// =====================================================================
// Launcher
// =====================================================================
extern "C" void kernel_launch(void* const* d_in, const int* in_sizes, int n_in,
                              void* d_out, int out_size)
{
    const float* x  = (const float*)d_in[0];
    const float* a  = (const float*)d_in[1];
    const float* b  = (const float*)d_in[2];
    const float* A  = (const float*)d_in[3];
    const float* B  = (const float*)d_in[4];
    const float* U  = (const float*)d_in[5];
    const float* V  = (const float*)d_in[6];
    const float* W  = (const float*)d_in[7];
    const float* a0 = (const float*)d_in[8];
    const float* A0 = (const float*)d_in[9];
    float* out = (float*)d_out;

    riccati_kernel<<<1, 256>>>(A, B, U, V, W, A0);
    prep_kernel<<<NCHUNK, 256>>>(A, B, a, b);
    passB_kernel<<<NCHUNK * 16, 128>>>(x);
    combine_kernel<<<16, 256>>>(a0);
    passD_kernel<<<NCHUNK * 16, 128>>>(x, b, B);
    reduce_kernel<<<1, 256>>>(out);
}